// round 1
// baseline (speedup 1.0000x reference)
#include <cuda_runtime.h>
#include <cstdint>
#include <cstddef>

// Problem constants (fixed-shape problem)
constexpr int BATCH = 16;
constexpr int C     = 256;
constexpr int NP    = 2048;
constexpr int CQ    = 64;
constexpr float EPSBN = 1e-3f;

// ---------------- scratch (static device buffers; no allocation) -------------
__device__ float g_h0[BATCH * C * NP];
__device__ float g_h1[BATCH * C * NP];
__device__ float g_q [BATCH * CQ * NP];
__device__ float g_attn[(size_t)BATCH * NP * NP];   // 268 MB
__device__ float g_xv[BATCH * C * NP];
__device__ float g_u [BATCH * C * NP];
__device__ float g_d [BATCH * NP];
__device__ float g_bnp[12 * C];  // [0]:a1 [1]:b1 [2]:a2 [3]:b2 [4..7]:aSA [8..11]:bSA(+tb folded)

// ---------------- BN prefold -------------------------------------------------
__global__ void bn_prep(const float* g1, const float* b1, const float* m1, const float* v1,
                        const float* g2, const float* b2, const float* m2, const float* v2,
                        const float* sg, const float* sb, const float* sm, const float* sv,
                        const float* stb)
{
    int c = threadIdx.x;
    int w = blockIdx.x;
    if (w == 0) {
        float a = g1[c] * rsqrtf(v1[c] + EPSBN);
        g_bnp[c] = a; g_bnp[C + c] = b1[c] - m1[c] * a;
    } else if (w == 1) {
        float a = g2[c] * rsqrtf(v2[c] + EPSBN);
        g_bnp[2*C + c] = a; g_bnp[3*C + c] = b2[c] - m2[c] * a;
    } else {
        int i = w - 2;
        float a = sg[i*C + c] * rsqrtf(sv[i*C + c] + EPSBN);
        g_bnp[(4+i)*C + c] = a;
        // bn(t_w@u + tb) = a*S + (b - m*a + a*tb)
        g_bnp[(8+i)*C + c] = sb[i*C + c] - sm[i*C + c] * a + a * stb[i*C + c];
    }
}

// ---------------- generic fp32 GEMM with fused epilogues ---------------------
enum { EPI_NONE = 0, EPI_BNRELU = 1, EPI_BIAS = 2, EPI_XR = 3, EPI_TOUT = 4 };

// C[m,n] = sum_k A[m,k] * B[k,n]   (per batch z)
// ATRANS: A stored K-major, i.e. A[k * M + m] (used for energy = q^T q)
template<int M, int N, int K, int BM, int BN, int TM, int TN, int MODE, bool ATRANS>
__global__ void __launch_bounds__((BM/TM)*(BN/TN))
gemm_f32(const float* __restrict__ A,  size_t sA,
         const float* __restrict__ Bp, size_t sB,
         float* __restrict__ Cp,       size_t sC,
         const float* __restrict__ e1,   // alpha / bias / h(XR) / alpha(TOUT)
         const float* __restrict__ e2,   // beta  /  d(XR)  / beta(TOUT)
         const float* __restrict__ e3,   // h (TOUT)
         float* __restrict__ out2)       // second output (TOUT), pre-offset by layer
{
    constexpr int BK = 8;
    constexpr int THREADS = (BM/TM) * (BN/TN);
    constexpr int LDA = ATRANS ? M : K;

    __shared__ float As[BK][BM];
    __shared__ float Bs[BK][BN];

    const int tid = threadIdx.x;
    const int b   = blockIdx.z;
    const int m0  = blockIdx.y * BM;
    const int n0  = blockIdx.x * BN;

    const float* Ab = A  + (size_t)b * sA;
    const float* Bb = Bp + (size_t)b * sB;

    float acc[TM][TN];
    #pragma unroll
    for (int i = 0; i < TM; i++)
        #pragma unroll
        for (int j = 0; j < TN; j++) acc[i][j] = 0.f;

    const int tx = tid % (BN/TN);
    const int ty = tid / (BN/TN);

    for (int k0 = 0; k0 < K; k0 += BK) {
        // ---- load A tile ----
        #pragma unroll
        for (int s = tid; s < BM*BK/4; s += THREADS) {
            if (ATRANS) {
                int kk = s / (BM/4), q4 = s % (BM/4);
                *(float4*)&As[kk][q4*4] =
                    *(const float4*)(Ab + (size_t)(k0 + kk) * LDA + m0 + q4*4);
            } else {
                int row = s / (BK/4), q4 = s % (BK/4);
                float4 v = *(const float4*)(Ab + (size_t)(m0 + row) * LDA + k0 + q4*4);
                As[q4*4+0][row] = v.x; As[q4*4+1][row] = v.y;
                As[q4*4+2][row] = v.z; As[q4*4+3][row] = v.w;
            }
        }
        // ---- load B tile ----
        #pragma unroll
        for (int s = tid; s < BK*BN/4; s += THREADS) {
            int kk = s / (BN/4), q4 = s % (BN/4);
            *(float4*)&Bs[kk][q4*4] =
                *(const float4*)(Bb + (size_t)(k0 + kk) * N + n0 + q4*4);
        }
        __syncthreads();

        #pragma unroll
        for (int k = 0; k < BK; k++) {
            float rm[TM], rn[TN];
            #pragma unroll
            for (int i = 0; i < TM; i += 4)
                *(float4*)&rm[i] = *(const float4*)&As[k][ty*TM + i];
            #pragma unroll
            for (int j = 0; j < TN; j += 4)
                *(float4*)&rn[j] = *(const float4*)&Bs[k][tx*TN + j];
            #pragma unroll
            for (int i = 0; i < TM; i++)
                #pragma unroll
                for (int j = 0; j < TN; j++)
                    acc[i][j] = fmaf(rm[i], rn[j], acc[i][j]);
        }
        __syncthreads();
    }

    float* Cb = Cp + (size_t)b * sC;
    const int gm0 = m0 + ty*TM;
    const int gn0 = n0 + tx*TN;

    #pragma unroll
    for (int i = 0; i < TM; i++) {
        const int gm = gm0 + i;
        #pragma unroll
        for (int j0 = 0; j0 < TN; j0 += 4) {
            float4 v;
            float* pv = &v.x;
            #pragma unroll
            for (int j = 0; j < 4; j++) {
                const int gn = gn0 + j0 + j;
                float s = acc[i][j0 + j];
                float r;
                if (MODE == EPI_NONE) {
                    r = s;
                } else if (MODE == EPI_BNRELU) {
                    r = fmaxf(fmaf(e1[gm], s, e2[gm]), 0.f);
                } else if (MODE == EPI_BIAS) {
                    r = s + e1[gm];
                } else if (MODE == EPI_XR) {
                    float dd = e2[(size_t)b * NP + gn];
                    r = e1[(size_t)b * C * NP + (size_t)gm * NP + gn] - s / (1e-9f + dd);
                } else { // EPI_TOUT
                    float t = fmaxf(fmaf(e1[gm], s, e2[gm]), 0.f);
                    r = e3[(size_t)b * C * NP + (size_t)gm * NP + gn] + t;
                }
                pv[j] = r;
            }
            *(float4*)&Cb[(size_t)gm * N + gn0 + j0] = v;
            if (MODE == EPI_TOUT)
                *(float4*)&out2[(size_t)b * 4 * C * NP + (size_t)gm * N + gn0 + j0] = v;
        }
    }
}

// ---------------- row softmax (in place) -------------------------------------
__global__ void __launch_bounds__(256) softmax_rows(float* __restrict__ P)
{
    const int tid = threadIdx.x;
    float* p = P + ((size_t)blockIdx.y * NP + blockIdx.x) * NP;

    float v[8];
    float mx = -3.4e38f;
    #pragma unroll
    for (int k = 0; k < 8; k++) { v[k] = p[tid + k*256]; mx = fmaxf(mx, v[k]); }

    #pragma unroll
    for (int o = 16; o > 0; o >>= 1) mx = fmaxf(mx, __shfl_xor_sync(0xffffffffu, mx, o));
    __shared__ float red[8];
    if ((tid & 31) == 0) red[tid >> 5] = mx;
    __syncthreads();
    mx = red[0];
    #pragma unroll
    for (int w = 1; w < 8; w++) mx = fmaxf(mx, red[w]);

    float s = 0.f;
    #pragma unroll
    for (int k = 0; k < 8; k++) { v[k] = __expf(v[k] - mx); s += v[k]; }
    #pragma unroll
    for (int o = 16; o > 0; o >>= 1) s += __shfl_xor_sync(0xffffffffu, s, o);
    __syncthreads();
    if ((tid & 31) == 0) red[tid >> 5] = s;
    __syncthreads();
    s = red[0];
    #pragma unroll
    for (int w = 1; w < 8; w++) s += red[w];

    const float inv = 1.f / s;
    #pragma unroll
    for (int k = 0; k < 8; k++) p[tid + k*256] = v[k] * inv;
}

// ---------------- column sums of P -------------------------------------------
__global__ void zero_d_kernel(float* d) { d[blockIdx.x * 256 + threadIdx.x] = 0.f; }

__global__ void __launch_bounds__(256) colsum_kernel(const float* __restrict__ P,
                                                     float* __restrict__ d)
{
    const int b = blockIdx.z;
    const int m = blockIdx.x * 256 + threadIdx.x;
    const int n0 = blockIdx.y * (NP / 8);
    const float* pb = P + (size_t)b * NP * NP;
    float s = 0.f;
    #pragma unroll 4
    for (int n = n0; n < n0 + NP/8; n++) s += pb[(size_t)n * NP + m];
    atomicAdd(&d[b * NP + m], s);
}

// ---------------- launch -----------------------------------------------------
extern "C" void kernel_launch(void* const* d_in, const int* in_sizes, int n_in,
                              void* d_out, int out_size)
{
    const float* x       = (const float*)d_in[0];
    const float* conv1_w = (const float*)d_in[1];
    const float* conv2_w = (const float*)d_in[2];
    const float* bn1_g = (const float*)d_in[3];
    const float* bn1_b = (const float*)d_in[4];
    const float* bn1_m = (const float*)d_in[5];
    const float* bn1_v = (const float*)d_in[6];
    const float* bn2_g = (const float*)d_in[7];
    const float* bn2_b = (const float*)d_in[8];
    const float* bn2_m = (const float*)d_in[9];
    const float* bn2_v = (const float*)d_in[10];
    const float* sa_qk_w = (const float*)d_in[11];  // [4, 64, 256]
    const float* sa_v_w  = (const float*)d_in[12];  // [4, 256, 256]
    const float* sa_v_b  = (const float*)d_in[13];  // [4, 256]
    const float* sa_t_w  = (const float*)d_in[14];  // [4, 256, 256]
    const float* sa_t_b  = (const float*)d_in[15];  // [4, 256]
    const float* sa_g    = (const float*)d_in[16];
    const float* sa_b    = (const float*)d_in[17];
    const float* sa_m    = (const float*)d_in[18];
    const float* sa_var  = (const float*)d_in[19];
    // d_in[20] = flag (0) -> primary bn branch; ignored.
    float* out = (float*)d_out;

    float *h0, *h1, *qb, *attn, *xv, *ub, *dcol, *bnp;
    cudaGetSymbolAddress((void**)&h0,   g_h0);
    cudaGetSymbolAddress((void**)&h1,   g_h1);
    cudaGetSymbolAddress((void**)&qb,   g_q);
    cudaGetSymbolAddress((void**)&attn, g_attn);
    cudaGetSymbolAddress((void**)&xv,   g_xv);
    cudaGetSymbolAddress((void**)&ub,   g_u);
    cudaGetSymbolAddress((void**)&dcol, g_d);
    cudaGetSymbolAddress((void**)&bnp,  g_bnp);

    const size_t sHN = (size_t)C * NP;        // h / xv / u batch stride
    const size_t sQ  = (size_t)CQ * NP;
    const size_t sP  = (size_t)NP * NP;

    bn_prep<<<6, 256>>>(bn1_g, bn1_b, bn1_m, bn1_v,
                        bn2_g, bn2_b, bn2_m, bn2_v,
                        sa_g, sa_b, sa_m, sa_var, sa_t_b);

    // conv1 -> h1 ; conv2 -> h0
    gemm_f32<256, 2048, 256, 128, 128, 8, 8, EPI_BNRELU, false>
        <<<dim3(16, 2, BATCH), 256>>>(conv1_w, 0, x, sHN, h1, sHN,
                                      bnp + 0, bnp + C, nullptr, nullptr);
    gemm_f32<256, 2048, 256, 128, 128, 8, 8, EPI_BNRELU, false>
        <<<dim3(16, 2, BATCH), 256>>>(conv2_w, 0, h1, sHN, h0, sHN,
                                      bnp + 2*C, bnp + 3*C, nullptr, nullptr);

    float* hcur = h0;
    float* hnxt = h1;
    for (int i = 0; i < 4; i++) {
        // q = qk_w @ h
        gemm_f32<64, 2048, 256, 64, 128, 4, 8, EPI_NONE, false>
            <<<dim3(16, 1, BATCH), 256>>>(sa_qk_w + (size_t)i * CQ * C, 0,
                                          hcur, sHN, qb, sQ,
                                          nullptr, nullptr, nullptr, nullptr);
        // energy = q^T q  (A is K-major)
        gemm_f32<2048, 2048, 64, 128, 128, 8, 8, EPI_NONE, true>
            <<<dim3(16, 16, BATCH), 256>>>(qb, sQ, qb, sQ, attn, sP,
                                           nullptr, nullptr, nullptr, nullptr);
        // row softmax in place
        softmax_rows<<<dim3(NP, BATCH), 256>>>(attn);
        // column sums d[b,m]
        zero_d_kernel<<<BATCH * NP / 256, 256>>>(dcol);
        colsum_kernel<<<dim3(NP / 256, 8, BATCH), 256>>>(attn, dcol);
        // xv = v_w @ h + v_b
        gemm_f32<256, 2048, 256, 128, 128, 8, 8, EPI_BIAS, false>
            <<<dim3(16, 2, BATCH), 256>>>(sa_v_w + (size_t)i * C * C, 0,
                                          hcur, sHN, xv, sHN,
                                          sa_v_b + (size_t)i * C, nullptr, nullptr, nullptr);
        // u = h - (xv @ P) / (1e-9 + d)
        gemm_f32<256, 2048, 2048, 128, 128, 8, 8, EPI_XR, false>
            <<<dim3(16, 2, BATCH), 256>>>(xv, sHN, attn, sP, ub, sHN,
                                          hcur, dcol, nullptr, nullptr);
        // h_next = h + relu(bn(t_w @ u + t_b));  also write output slice i
        gemm_f32<256, 2048, 256, 128, 128, 8, 8, EPI_TOUT, false>
            <<<dim3(16, 2, BATCH), 256>>>(sa_t_w + (size_t)i * C * C, 0,
                                          ub, sHN, hnxt, sHN,
                                          bnp + (4+i)*C, bnp + (8+i)*C, hcur,
                                          out + (size_t)i * C * NP);
        float* tmp = hcur; hcur = hnxt; hnxt = tmp;
    }
    (void)in_sizes; (void)n_in; (void)out_size;
}